// round 6
// baseline (speedup 1.0000x reference)
#include <cuda_runtime.h>

// GaussianBlur2D: depthwise 11x11 Gaussian blur, reflect padding.
// x: (16, 64, 512, 512) fp32, sigma: (1,) fp32.
//
// Separable, FFMA-bound -> packed fma.rn.f32x2 (sm_103a), halving fma-pipe
// instruction count:
//   - vertical 11-tap on a 14-row register window held as f32x2 pairs
//   - horizontal 11-tap as 2 packed accumulators over 13 overlapping pairs
//   - one STS.128 + 2 LDS.128 + 2 SHFL per row; 1 barrier / 4 rows
//   - software pipeline: LDGs for next rows issued before horizontal pass
// g2d[i][j] = (h[i]/S)*(h[j]/S) with S = sum(h)  == reference's 2D kernel.

#define KS    11
#define IMG   512
#define NT    128      // threads per block; NT*4 == IMG
#define RPT   4        // output rows per loop iteration
#define STRIP 128      // output rows per block
#define HB    8        // smem halo floats on each side
#define SVW   (HB + IMG + HB)   // 528
#define FULL  0xffffffffu

typedef unsigned long long ull;

#define FMA2(d, a, b, c) \
    asm("fma.rn.f32x2 %0, %1, %2, %3;" : "=l"(d) : "l"(a), "l"(b), "l"(c))
#define PACK2(out, lo, hi) \
    asm("mov.b64 %0, {%1, %2};" : "=l"(out) : "f"(lo), "f"(hi))
#define UNPACK2(lo, hi, in) \
    asm("mov.b64 {%0, %1}, %2;" : "=f"(lo), "=f"(hi) : "l"(in))

__device__ __forceinline__ int refl(int i) {
    i = (i < 0) ? -i : i;
    return (i >= IMG) ? (2 * IMG - 2 - i) : i;
}

__global__ __launch_bounds__(NT, 4)
void gaussian_blur_kernel(const float* __restrict__ in, float* __restrict__ out,
                          const float* __restrict__ sigma) {
    __shared__ __align__(16) float s_v[2][RPT][SVW];

    const int t    = threadIdx.x;
    const int lane = t & 31;
    const int x    = t << 2;                    // this thread owns columns x..x+3
    const int plane = blockIdx.x >> 2;
    const int y0 = (blockIdx.x & 3) * STRIP;
    const float* __restrict__ img  = in  + (size_t)plane * (IMG * IMG);
    float*       __restrict__ oimg = out + (size_t)plane * (IMG * IMG);

    // normalized 1D weights, packed {w,w} for f32x2
    ull w2[KS];
    {
        float s = fabsf(sigma[0]) + 1e-6f;
        float inv = 1.0f / (2.0f * s * s);
        float h[KS];
        float sum = 0.0f;
        #pragma unroll
        for (int j = 0; j < KS; j++) {
            float r = (float)j - (float)(KS - 1) * 0.5f;
            h[j] = __expf(-r * r * inv);
            sum += h[j];
        }
        float rs = 1.0f / sum;
        #pragma unroll
        for (int j = 0; j < KS; j++) {
            float wj = h[j] * rs;
            PACK2(w2[j], wj, wj);
        }
    }

    // win[k] = raw input row (yb + k - 5) as two f32x2 packs
    ulonglong2 win[14];
    #pragma unroll
    for (int k = 0; k < 14; k++)
        win[k] = *(const ulonglong2*)(img + (size_t)refl(y0 + k - 5) * IMG + x);

    // va0/va1 = current vblur quad (rows yb..yb+3), packed halves
    ull va0[RPT], va1[RPT];

    // vertical 11-tap for rows r0..r0+3 from win, store to smem buffer b
    auto vpass = [&](int b) {
        #pragma unroll
        for (int r = 0; r < RPT; r++) {
            ull a0 = 0ull, a1 = 0ull;
            #pragma unroll
            for (int i = 0; i < KS; i++) {
                FMA2(a0, w2[i], win[r + i].x, a0);
                FMA2(a1, w2[i], win[r + i].y, a1);
            }
            va0[r] = a0; va1[r] = a1;
            *(ulonglong2*)&s_v[b][r][HB + x] = make_ulonglong2(a0, a1);
            if (t <= 2 || t >= 125) {            // halo mirror (edge threads only)
                float f0, f1, f2, f3;
                UNPACK2(f0, f1, a0);
                UNPACK2(f2, f3, a1);
                const float av[4] = {f0, f1, f2, f3};
                #pragma unroll
                for (int c = 0; c < 4; c++) {
                    const int xc = x + c;
                    if (xc >= 1 && xc <= HB)            s_v[b][r][HB - xc]        = av[c];
                    if (xc >= IMG - 1 - HB && xc <= IMG - 2)
                                                        s_v[b][r][HB + 1022 - xc] = av[c];
                }
            }
        }
    };

    // prologue: vblur rows y0..y0+3
    vpass(0);
    __syncthreads();

    int buf = 0;
    for (int yb = 0; ; yb += RPT) {
        const int y = y0 + yb;
        const bool last = (yb + RPT >= STRIP);

        // slide window, issue LDGs for rows y+9..y+12 (fly during horizontal)
        if (!last) {
            #pragma unroll
            for (int k = 0; k < 14 - RPT; k++) win[k] = win[k + RPT];
            #pragma unroll
            for (int r = 0; r < RPT; r++)
                win[10 + r] = *(const ulonglong2*)(img + (size_t)refl(y + 9 + r) * IMG + x);
        }

        // ---- horizontal 11-tap for rows y..y+3 (packed pairs) ----
        #pragma unroll
        for (int r = 0; r < RPT; r++) {
            float qx, qy, qz, qw;
            UNPACK2(qx, qy, va0[r]);
            UNPACK2(qz, qw, va1[r]);
            const float4 L = *(const float4*)&s_v[buf][r][HB + x - 4]; // x-4..x-1
            const float4 R = *(const float4*)&s_v[buf][r][HB + x + 4]; // x+4..x+7

            float v0  = __shfl_up_sync  (FULL, qw, 2);    // col x-5
            float v13 = __shfl_down_sync(FULL, qx, 2);    // col x+8
            if (lane < 2)   v0  = s_v[buf][r][HB + x - 5];
            if (lane >= 30) v13 = s_v[buf][r][HB + x + 8];

            ull p[13];
            PACK2(p[0],  v0,  L.x); PACK2(p[1],  L.x, L.y);
            PACK2(p[2],  L.y, L.z); PACK2(p[3],  L.z, L.w);
            PACK2(p[4],  L.w, qx);  p[5] = va0[r];
            PACK2(p[6],  qy,  qz);  p[7] = va1[r];
            PACK2(p[8],  qw,  R.x); PACK2(p[9],  R.x, R.y);
            PACK2(p[10], R.y, R.z); PACK2(p[11], R.z, R.w);
            PACK2(p[12], R.w, v13);

            ull o01 = 0ull, o23 = 0ull;
            #pragma unroll
            for (int j = 0; j < KS; j++) {
                FMA2(o01, w2[j], p[j],     o01);
                FMA2(o23, w2[j], p[j + 2], o23);
            }
            *(ulonglong2*)(oimg + (size_t)(y + r) * IMG + x) = make_ulonglong2(o01, o23);
        }

        if (last) break;

        // ---- vertical for rows y+4..y+7 into the other buffer ----
        vpass(buf ^ 1);
        __syncthreads();
        buf ^= 1;
    }
}

extern "C" void kernel_launch(void* const* d_in, const int* in_sizes, int n_in,
                              void* d_out, int out_size) {
    const float* x     = (const float*)d_in[0];
    const float* sigma = (const float*)d_in[1];
    float*       out   = (float*)d_out;

    const int n_img = in_sizes[0] / (IMG * IMG);   // B*C planes

    const int strips = IMG / STRIP;                // 4
    gaussian_blur_kernel<<<n_img * strips, NT>>>(x, out, sigma);
}